// round 2
// baseline (speedup 1.0000x reference)
#include <cuda_runtime.h>

// Transducer loss on GB300.
// Phase 1: lse2[b,t] = log2-sum-exp2 over C classes (parallel, HBM-bound).
// Phase 2: serial T-step recurrence, one block per batch, one thread per label,
//          one __syncthreads per step, register-pipelined gathers.
// Phase 3: deterministic mean over batch.

#define NEGF (-1e30f)
#define INV_LN2 1.44269504088896340736f
#define LN2_F 0.69314718055994530942f

static constexpr int B = 128;
static constexpr int T = 2000;
static constexpr int C = 62;
static constexpr int L = 256;

__device__ float g_lse2[B * T];   // scratch: log2-domain logsumexp per (b,t)
__device__ float g_bloss[B];      // scratch: per-batch loss

static __device__ __forceinline__ float ex2f(float x) {
    float y; asm("ex2.approx.ftz.f32 %0, %1;" : "=f"(y) : "f"(x)); return y;
}
static __device__ __forceinline__ float lg2f(float x) {
    float y; asm("lg2.approx.ftz.f32 %0, %1;" : "=f"(y) : "f"(x)); return y;
}

// ---------------------------------------------------------------------------
// Kernel 1: per-row logsumexp in log2 domain. One warp per (b,t) row.
// 8 warps / block. Reads the full 63.5MB input once.
// ---------------------------------------------------------------------------
__global__ __launch_bounds__(256) void lse_kernel(const float* __restrict__ x) {
    const int warp = threadIdx.x >> 5;
    const int lane = threadIdx.x & 31;
    const long row = (long)blockIdx.x * 8 + warp;
    if (row >= (long)B * T) return;

    const float* r = x + row * C;
    float a = (lane < C) ? __ldg(r + lane) * INV_LN2 : NEGF;
    float b = (lane + 32 < C) ? __ldg(r + lane + 32) * INV_LN2 : NEGF;

    float m = fmaxf(a, b);
#pragma unroll
    for (int o = 16; o; o >>= 1) m = fmaxf(m, __shfl_xor_sync(0xffffffffu, m, o));

    float s = ex2f(a - m) + ex2f(b - m);
#pragma unroll
    for (int o = 16; o; o >>= 1) s += __shfl_xor_sync(0xffffffffu, s, o);

    if (lane == 0) g_lse2[row] = m + lg2f(s);
}

// ---------------------------------------------------------------------------
// Kernel 2: the serial recurrence. One block per batch element, 256 threads
// (one per label u). alpha kept in a register; left neighbor exchanged through
// a double-buffered shared array -> exactly one barrier per time step.
// Gathered emissions + lse are loaded K steps ahead into registers so global
// latency never sits on the critical path.
// ---------------------------------------------------------------------------
__global__ __launch_bounds__(L, 1) void recur_kernel(const float* __restrict__ x,
                                                     const int* __restrict__ tg) {
    const int b = blockIdx.x;
    const int u = threadIdx.x;

    __shared__ float sh[2][L];

    const int tgt = __ldg(tg + b * L + u);
    const float* xp = x + (long)b * T * C + tgt;   // emission column for this label
    const float* lp = g_lse2 + b * T;

    // t = 0 init: only u==0 is reachable.
    float alpha = (u == 0) ? fmaf(__ldg(xp), INV_LN2, -__ldg(lp)) : NEGF;

    constexpr int K = 8;   // software-pipeline depth for gathers
    float xq[K], lq[K];
#pragma unroll
    for (int k = 0; k < K; k++) {
        xq[k] = __ldg(xp + (long)(1 + k) * C);
        lq[k] = __ldg(lp + 1 + k);
    }

    int p = 0;
    sh[0][u] = alpha;
    __syncthreads();

    for (int tb = 1; tb < T; tb += K) {
#pragma unroll
        for (int k = 0; k < K; k++) {
            const int t = tb + k;
            if (t < T) {
                const float em = fmaf(xq[k], INV_LN2, -lq[k]);
                const int tn = t + K;
                if (tn < T) {   // prefetch K steps ahead (off critical path)
                    xq[k] = __ldg(xp + (long)tn * C);
                    lq[k] = __ldg(lp + tn);
                }
                const float left = (u == 0) ? NEGF : sh[p][u - 1];
                const float m = fmaxf(alpha, left);
                const float d = -fabsf(alpha - left);
                const float f = lg2f(1.0f + ex2f(d));   // log2(1 + 2^d), d <= 0
                alpha = m + f + em;
                p ^= 1;
                sh[p][u] = alpha;
                __syncthreads();
            }
        }
    }

    if (u == L - 1) g_bloss[b] = -alpha * LN2_F;
}

// ---------------------------------------------------------------------------
// Kernel 3: deterministic mean over the batch (no atomics).
// ---------------------------------------------------------------------------
__global__ __launch_bounds__(128) void reduce_kernel(float* __restrict__ out) {
    const int i = threadIdx.x;   // 128 threads
    float v = g_bloss[i];
#pragma unroll
    for (int o = 16; o; o >>= 1) v += __shfl_xor_sync(0xffffffffu, v, o);

    __shared__ float ws[4];
    if ((i & 31) == 0) ws[i >> 5] = v;
    __syncthreads();
    if (i == 0) out[0] = (ws[0] + ws[1] + ws[2] + ws[3]) * (1.0f / (float)B);
}

// ---------------------------------------------------------------------------
extern "C" void kernel_launch(void* const* d_in, const int* in_sizes, int n_in,
                              void* d_out, int out_size) {
    const float* x = (const float*)d_in[0];   // [B, T, C] float32
    const int* tg = (const int*)d_in[1];      // [B, L] int32
    float* out = (float*)d_out;

    (void)in_sizes; (void)n_in; (void)out_size;

    lse_kernel<<<(B * T + 7) / 8, 256>>>(x);
    recur_kernel<<<B, L>>>(x, tg);
    reduce_kernel<<<1, 128>>>(out);
}